// round 12
// baseline (speedup 1.0000x reference)
#include <cuda_runtime.h>
#include <math.h>
#include <stdint.h>

// Problem constants
#define S_LEN 2048
#define EDIM  1024
#define NH    8
#define DH    128
#define BM    64
#define BN    64
#define NT    512

typedef unsigned long long ull;

// ---- packed f32x2 helpers (Blackwell FFMA2 — PTX-only path) ----
__device__ __forceinline__ ull ffma2(ull a, ull b, ull c) {
    ull d;
    asm("fma.rn.f32x2 %0, %1, %2, %3;" : "=l"(d) : "l"(a), "l"(b), "l"(c));
    return d;
}
__device__ __forceinline__ ull fmul2(ull a, ull b) {
    ull d;
    asm("mul.rn.f32x2 %0, %1, %2;" : "=l"(d) : "l"(a), "l"(b));
    return d;
}
__device__ __forceinline__ ull dup2f(float x) {
    ull d;
    asm("mov.b64 %0, {%1, %1};" : "=l"(d) : "f"(x));
    return d;
}
__device__ __forceinline__ void unpk2(ull v, float& lo, float& hi) {
    asm("mov.b64 {%0, %1}, %2;" : "=f"(lo), "=f"(hi) : "l"(v));
}
__device__ __forceinline__ void cp16(uint32_t dst, const float* src) {
    asm volatile("cp.async.cg.shared.global [%0], [%1], 16;" :: "r"(dst), "l"(src));
}
__device__ __forceinline__ void cp_commit() {
    asm volatile("cp.async.commit_group;");
}
__device__ __forceinline__ void cp_wait0() {
    asm volatile("cp.async.wait_group 0;");
}

// Scratch (device globals: no allocations allowed)
__device__ float g_ig   [NH * S_LEN];
__device__ float g_logf [NH * S_LEN];
__device__ float g_cumS [NH * S_LEN];   // inclusive scan of log_f
__device__ float g_B    [NH * S_LEN];   // B[t] = ig[t] - cum[t]
__device__ float g_pm   [NH * S_LEN];   // prefix max of B (inclusive)
__device__ float g_tileb[NH * 32];      // per-64-tile max of B
__device__ float g_h    [S_LEN * EDIM];

// ---------------------------------------------------------------------------
// Kernel 1: gate projections.
// ---------------------------------------------------------------------------
__global__ void gates_kernel(const float* __restrict__ q,
                             const float* __restrict__ k,
                             const float* __restrict__ v,
                             const float* __restrict__ Wi,
                             const float* __restrict__ bi,
                             const float* __restrict__ Wf,
                             const float* __restrict__ bf) {
    const int b = blockIdx.x;
    const int tid = threadIdx.x;

    float acc[64];
#pragma unroll
    for (int i = 0; i < 64; i++) acc[i] = 0.f;

#pragma unroll 1
    for (int it = 0; it < 12; it++) {
        const int j = it * 256 + tid;
        float wi[8], wf[8];
#pragma unroll
        for (int h = 0; h < 8; h++) {
            wi[h] = Wi[h * 3072 + j];
            wf[h] = Wf[h * 3072 + j];
        }
#pragma unroll
        for (int r = 0; r < 4; r++) {
            const int s = b * 4 + r;
            float x;
            if (j < 1024)       x = q[s * 1024 + j];
            else if (j < 2048)  x = k[s * 1024 + (j - 1024)];
            else                x = v[s * 1024 + (j - 2048)];
#pragma unroll
            for (int h = 0; h < 8; h++) {
                acc[r * 16 + h]     = fmaf(x, wi[h], acc[r * 16 + h]);
                acc[r * 16 + 8 + h] = fmaf(x, wf[h], acc[r * 16 + 8 + h]);
            }
        }
    }

#pragma unroll
    for (int i = 0; i < 64; i++) {
#pragma unroll
        for (int off = 16; off > 0; off >>= 1)
            acc[i] += __shfl_xor_sync(0xffffffffu, acc[i], off);
    }
    __shared__ float red[8][64];
    const int warp = tid >> 5, lane = tid & 31;
    if (lane == 0) {
#pragma unroll
        for (int i = 0; i < 64; i++) red[warp][i] = acc[i];
    }
    __syncthreads();
    if (tid < 64) {
        float vsum = 0.f;
#pragma unroll
        for (int w = 0; w < 8; w++) vsum += red[w][tid];
        const int r = tid >> 4;
        const int o = tid & 15;
        const int h = o & 7;
        const int s = b * 4 + r;
        if (o < 8) {
            g_ig[h * S_LEN + s] = vsum + bi[h];
        } else {
            const float fg = vsum + bf[h];
            g_logf[h * S_LEN + s] = fminf(fg, 0.f) - log1pf(expf(-fabsf(fg)));
        }
    }
}

// ---------------------------------------------------------------------------
// Kernel 2: per-head scan: cum (double), B, prefix-max(B), per-tile max(B).
// ---------------------------------------------------------------------------
__global__ void scan_kernel() {
    const int h = blockIdx.x;
    const int tid = threadIdx.x;
    const int lane = tid & 31, warp = tid >> 5;

    const double x0 = (double)g_logf[h * S_LEN + 2 * tid];
    const double x1 = (double)g_logf[h * S_LEN + 2 * tid + 1];
    const double s = x0 + x1;

    double inc = s;
#pragma unroll
    for (int off = 1; off < 32; off <<= 1) {
        double u = __shfl_up_sync(0xffffffffu, inc, off);
        if (lane >= off) inc += u;
    }
    __shared__ double wsum[32];
    if (lane == 31) wsum[warp] = inc;
    __syncthreads();
    if (warp == 0) {
        double w = wsum[lane];
#pragma unroll
        for (int off = 1; off < 32; off <<= 1) {
            double u = __shfl_up_sync(0xffffffffu, w, off);
            if (lane >= off) w += u;
        }
        wsum[lane] = w;
    }
    __syncthreads();
    const double base = (warp > 0) ? wsum[warp - 1] : 0.0;
    const double incl = base + inc;
    const double excl = incl - s;

    const float c0 = (float)(excl + x0);
    const float c1 = (float)incl;
    g_cumS[h * S_LEN + 2 * tid]     = c0;
    g_cumS[h * S_LEN + 2 * tid + 1] = c1;

    const float B0 = g_ig[h * S_LEN + 2 * tid]     - c0;
    const float B1 = g_ig[h * S_LEN + 2 * tid + 1] - c1;
    g_B[h * S_LEN + 2 * tid]     = B0;
    g_B[h * S_LEN + 2 * tid + 1] = B1;

    const float mx = fmaxf(B0, B1);

    float tb = mx;
#pragma unroll
    for (int off = 16; off > 0; off >>= 1)
        tb = fmaxf(tb, __shfl_xor_sync(0xffffffffu, tb, off));
    if (lane == 0) g_tileb[h * 32 + warp] = tb;

    float im = mx;
#pragma unroll
    for (int off = 1; off < 32; off <<= 1) {
        float u = __shfl_up_sync(0xffffffffu, im, off);
        if (lane >= off) im = fmaxf(im, u);
    }
    __shared__ float wm[32];
    if (lane == 31) wm[warp] = im;
    __syncthreads();
    if (warp == 0) {
        float w = wm[lane];
#pragma unroll
        for (int off = 1; off < 32; off <<= 1) {
            float u = __shfl_up_sync(0xffffffffu, w, off);
            if (lane >= off) w = fmaxf(w, u);
        }
        wm[lane] = w;
    }
    __syncthreads();
    const float bmbase = (warp > 0) ? wm[warp - 1] : -INFINITY;
    const float wexcl = __shfl_up_sync(0xffffffffu, im, 1);
    const float exclm = fmaxf(bmbase, (lane > 0) ? wexcl : -INFINITY);
    const float pm0 = fmaxf(exclm, B0);
    const float pm1 = fmaxf(pm0, B1);
    g_pm[h * S_LEN + 2 * tid]     = pm0;
    g_pm[h * S_LEN + 2 * tid + 1] = pm1;
}

// ---------------------------------------------------------------------------
// Kernel 3: main kernel. 512 threads (4 warps/SMSP), double-buffered K/V,
// precomputed row-max (no rescale). 2x4 micro-tiles.
// grid 256 = (32 qtiles x 8 heads).
// ---------------------------------------------------------------------------
#define QS_OFF 0
#define KS_OFF (64 * 128)                  // Q: 8192 floats (swizzled)
#define VS_OFF (KS_OFF + 2 * 64 * 128)     // K db: 16384
#define PS_OFF (VS_OFF + 2 * 64 * 128)     // V db: 16384
#define SMEM_FLOATS (PS_OFF + 64 * 68)     // P: 4352 -> 45312 fl = 181248 B
#define SMEM_BYTES (SMEM_FLOATS * 4)

// swizzled [64][128] tile: row r, 4-float chunk ch at (r*128 + ((ch^swz(r))<<2))
__device__ __forceinline__ void prefetch_swz(const float* __restrict__ g,
                                             float* sb, int tid) {
    uint32_t base = (uint32_t)__cvta_generic_to_shared(sb);
#pragma unroll
    for (int it = 0; it < 4; it++) {
        const int c = it * NT + tid;
        const int row = c >> 5, ch = c & 31;
        const int swz = (row ^ (row >> 3)) & 7;
        cp16(base + (uint32_t)(row * 128 + ((ch ^ swz) << 2)) * 4u,
             g + row * EDIM + ch * 4);
    }
}
__device__ __forceinline__ void prefetch_V(const float* __restrict__ vg,
                                           float* Vsb, int tid) {
    uint32_t vbase = (uint32_t)__cvta_generic_to_shared(Vsb);
#pragma unroll
    for (int it = 0; it < 4; it++) {
        const int c = it * NT + tid;
        const int key = c >> 5, ch = c & 31;
        cp16(vbase + (uint32_t)(key * 128 + (ch << 2)) * 4u,
             vg + key * EDIM + ch * 4);
    }
}

extern "C" __global__ void __launch_bounds__(NT, 1)
mlstm_main_kernel(const float* __restrict__ q,
                  const float* __restrict__ k,
                  const float* __restrict__ v) {
    extern __shared__ float sm[];
    float* Qs  = sm + QS_OFF;    // [64][128] swizzled
    float* Ks0 = sm + KS_OFF;    // [64][128] swizzled, double-buffered
    float* Vs0 = sm + VS_OFF;    // [64][128] double-buffered
    float* Ps  = sm + PS_OFF;    // [64][68]  Ps[key][row]

    const int bx = blockIdx.x;
    const int qi = 31 - (bx >> 3);       // longest-work-first
    const int h  = bx & 7;
    const int tid = threadIdx.x;
    const int tx = tid & 15;             // keys 4tx..4tx+3; dims tx*4, 64+tx*4
    const int ty = tid >> 4;             // 0..31: rows 2ty, 2ty+1

    const float scale = 0.08838834764831845f;  // 1/sqrt(128)
    const float* kg0 = k + h * DH;
    const float* vg0 = v + h * DH;
    const int qrow0 = qi * BM;

    // prefetch: {Q} then {K0,V0}
    prefetch_swz(q + (size_t)qrow0 * EDIM + h * DH, Qs, tid);
    cp_commit();
    prefetch_swz(kg0, Ks0, tid);
    prefetch_V(vg0, Vs0, tid);
    cp_commit();

    float pm[2];
    int srow[2];
#pragma unroll
    for (int i = 0; i < 2; i++) {
        srow[i] = qrow0 + ty * 2 + i;
        pm[i] = g_pm[h * S_LEN + srow[i]];
    }

    int kswz[4], qswz[2];
#pragma unroll
    for (int j = 0; j < 4; j++) {
        const int rk = 4 * tx + j;
        kswz[j] = (rk ^ (rk >> 3)) & 7;
    }
#pragma unroll
    for (int i = 0; i < 2; i++) {
        const int rq = 2 * ty + i;
        qswz[i] = (rq ^ (rq >> 3)) & 7;
    }

    float lpart[2];
    ull o2[2][4];
#pragma unroll
    for (int i = 0; i < 2; i++) {
        lpart[i] = 0.f;
#pragma unroll
        for (int d = 0; d < 4; d++) o2[i][d] = 0ull;
    }

    cp_wait0();
    __syncthreads();

    for (int kt = 0; kt <= qi; kt++) {
        const int t0 = kt * BN;
        float* Kb = Ks0 + (kt & 1) * (64 * 128);
        float* Vb = Vs0 + (kt & 1) * (64 * 128);

        const int c0 = tx * 4;
        const float4 Bv = *(const float4*)(g_B + h * S_LEN + t0 + c0);
        const float Bc[4] = {Bv.x, Bv.y, Bv.z, Bv.w};
        const float tb = g_tileb[h * 32 + kt];

        // ---- QK^T 64x64x128, 2x4 micro-tile, packed pairs ----
        ull acc2[2][4];
#pragma unroll
        for (int i = 0; i < 2; i++)
#pragma unroll
            for (int j = 0; j < 4; j++) acc2[i][j] = 0ull;

#pragma unroll 8
        for (int ch = 0; ch < 32; ch++) {
            ulonglong2 qv[2], kv[4];
#pragma unroll
            for (int i = 0; i < 2; i++)
                qv[i] = *(const ulonglong2*)(Qs + (2 * ty + i) * 128 + ((ch ^ qswz[i]) << 2));
#pragma unroll
            for (int j = 0; j < 4; j++)
                kv[j] = *(const ulonglong2*)(Kb + (4 * tx + j) * 128 + ((ch ^ kswz[j]) << 2));
#pragma unroll
            for (int i = 0; i < 2; i++)
#pragma unroll
                for (int j = 0; j < 4; j++) {
                    acc2[i][j] = ffma2(qv[i].x, kv[j].x, acc2[i][j]);
                    acc2[i][j] = ffma2(qv[i].y, kv[j].y, acc2[i][j]);
                }
        }
        float acc[2][4];
#pragma unroll
        for (int i = 0; i < 2; i++)
#pragma unroll
            for (int j = 0; j < 4; j++) {
                float lo, hi; unpk2(acc2[i][j], lo, hi);
                acc[i][j] = lo + hi;
            }

        // ---- gate math: no reductions, no rescaling ----
        float P[2][4];
        if (kt < qi) {
            float eB[4];
#pragma unroll
            for (int j = 0; j < 4; j++) eB[j] = __expf(Bc[j] - tb);
#pragma unroll
            for (int i = 0; i < 2; i++) {
                const float eA = scale * __expf(tb - pm[i]);
                float rs = 0.f;
#pragma unroll
                for (int j = 0; j < 4; j++) {
                    const float p = acc[i][j] * (eA * eB[j]);
                    P[i][j] = p;
                    rs += p;
                }
                lpart[i] += rs;
            }
        } else {
#pragma unroll
            for (int i = 0; i < 2; i++) {
                float rs = 0.f;
#pragma unroll
                for (int j = 0; j < 4; j++) {
                    const bool ok = (4 * tx + j <= 2 * ty + i);
                    const float p = ok ? acc[i][j] * (scale * __expf(Bc[j] - pm[i])) : 0.f;
                    P[i][j] = p;
                    rs += p;
                }
                lpart[i] += rs;
            }
        }

        // stage P to smem: Ps[key][row], float2 per key
#pragma unroll
        for (int j = 0; j < 4; j++) {
            float2 pv = make_float2(P[0][j], P[1][j]);
            *(float2*)(Ps + (c0 + j) * 68 + ty * 2) = pv;
        }
        __syncthreads();   // Ps visible; QK done by all

        if (kt < qi) {
            prefetch_swz(kg0 + (size_t)(t0 + BN) * EDIM,
                         Ks0 + ((kt + 1) & 1) * (64 * 128), tid);
            prefetch_V(vg0 + (size_t)(t0 + BN) * EDIM,
                       Vs0 + ((kt + 1) & 1) * (64 * 128), tid);
            cp_commit();
        }

        // ---- P @ V (packed f32x2), dims 4tx..+3 and 64+4tx..+3 ----
#pragma unroll 8
        for (int tt = 0; tt < 64; tt++) {
            const float2 p2 = *(const float2*)(Ps + tt * 68 + ty * 2);
            const ulonglong2 va = *(const ulonglong2*)(Vb + tt * 128 + tx * 4);
            const ulonglong2 vb = *(const ulonglong2*)(Vb + tt * 128 + 64 + tx * 4);
            const float pa[2] = {p2.x, p2.y};
#pragma unroll
            for (int i = 0; i < 2; i++) {
                const ull pd = dup2f(pa[i]);
                o2[i][0] = ffma2(pd, va.x, o2[i][0]);
                o2[i][1] = ffma2(pd, va.y, o2[i][1]);
                o2[i][2] = ffma2(pd, vb.x, o2[i][2]);
                o2[i][3] = ffma2(pd, vb.y, o2[i][3]);
            }
        }

        if (kt < qi) cp_wait0();
        __syncthreads();   // next tile ready; PV done (buffers rotatable)
    }

    // ---- epilogue: reduce lpart over the 16 tx lanes (width-16 shfl) ----
#pragma unroll
    for (int i = 0; i < 2; i++) {
#pragma unroll
        for (int off = 1; off < 16; off <<= 1)
            lpart[i] += __shfl_xor_sync(0xffffffffu, lpart[i], off, 16);
    }

#pragma unroll
    for (int i = 0; i < 2; i++) {
        const float l = lpart[i];
        const float cumq = g_cumS[h * S_LEN + srow[i]];
        const float norm = fmaxf(fabsf(l), __expf(-(cumq + pm[i]))) + 1e-6f;
        const ull iv = dup2f(1.f / norm);
        float* dst = g_h + (size_t)srow[i] * EDIM + h * DH;
        ulonglong2 ra, rb;
        ra.x = fmul2(o2[i][0], iv); ra.y = fmul2(o2[i][1], iv);
        rb.x = fmul2(o2[i][2], iv); rb.y = fmul2(o2[i][3], iv);
        *(ulonglong2*)(dst + tx * 4)      = ra;
        *(ulonglong2*)(dst + 64 + tx * 4) = rb;
    }
}

// ---------------------------------------------------------------------------
// Kernel 4: residual layer norm.
// ---------------------------------------------------------------------------
__global__ void ln_kernel(const float* __restrict__ lnw, float* __restrict__ out) {
    const int s = blockIdx.x;
    const int tid = threadIdx.x;
    const int lane = tid & 31, warp = tid >> 5;

    const float4 x = *(const float4*)(g_h + s * EDIM + tid * 4);

    __shared__ float wsum[8];
    __shared__ float stat[2];

    float lsum = x.x + x.y + x.z + x.w;
#pragma unroll
    for (int off = 16; off > 0; off >>= 1)
        lsum += __shfl_xor_sync(0xffffffffu, lsum, off);
    if (lane == 0) wsum[warp] = lsum;
    __syncthreads();
    if (tid == 0) {
        float t = 0.f;
#pragma unroll
        for (int w = 0; w < 8; w++) t += wsum[w];
        stat[0] = t * (1.f / 1024.f);
    }
    __syncthreads();
    const float mean = stat[0];

    const float d0 = x.x - mean, d1 = x.y - mean, d2 = x.z - mean, d3 = x.w - mean;
    float lsq = d0 * d0 + d1 * d1 + d2 * d2 + d3 * d3;
#pragma unroll
    for (int off = 16; off > 0; off >>= 1)
        lsq += __shfl_xor_sync(0xffffffffu, lsq, off);
    if (lane == 0) wsum[warp] = lsq;
    __syncthreads();
    if (tid == 0) {
        float t = 0.f;
#pragma unroll
        for (int w = 0; w < 8; w++) t += wsum[w];
        stat[1] = rsqrtf(t * (1.f / 1024.f) + 1e-5f);
    }
    __syncthreads();
    const float rstd = stat[1];

    const float4 w4 = *(const float4*)(lnw + tid * 4);
    float4 r;
    r.x = d0 * rstd * (1.f + w4.x);
    r.y = d1 * rstd * (1.f + w4.y);
    r.z = d2 * rstd * (1.f + w4.z);
    r.w = d3 * rstd * (1.f + w4.w);
    *(float4*)(out + s * EDIM + tid * 4) = r;
}

// ---------------------------------------------------------------------------
extern "C" void kernel_launch(void* const* d_in, const int* in_sizes, int n_in,
                              void* d_out, int out_size) {
    const float* q   = (const float*)d_in[0];
    const float* k   = (const float*)d_in[1];
    const float* v   = (const float*)d_in[2];
    const float* Wi  = (const float*)d_in[3];
    const float* bi  = (const float*)d_in[4];
    const float* Wf  = (const float*)d_in[5];
    const float* bf  = (const float*)d_in[6];
    const float* lnw = (const float*)d_in[7];
    float* out = (float*)d_out;

    gates_kernel<<<S_LEN / 4, 256>>>(q, k, v, Wi, bi, Wf, bf);
    scan_kernel<<<NH, 1024>>>();

    cudaFuncSetAttribute(mlstm_main_kernel,
                         cudaFuncAttributeMaxDynamicSharedMemorySize, SMEM_BYTES);
    mlstm_main_kernel<<<32 * NH, NT, SMEM_BYTES>>>(q, k, v);

    ln_kernel<<<S_LEN, 256>>>(lnw, out);
}

// round 15
// speedup vs baseline: 1.8630x; 1.8630x over previous
#include <cuda_runtime.h>
#include <cuda_bf16.h>
#include <math.h>
#include <stdint.h>

// Problem constants
#define S_LEN 2048
#define EDIM  1024
#define NH    8
#define DH    128
#define BM    128          // query rows per CTA
#define BN    64           // keys per tile
#define NT    256

// ---------------------------------------------------------------------------
// Scratch (device globals: no allocations allowed)
__device__ float g_ig   [NH * S_LEN];
__device__ float g_logf [NH * S_LEN];
__device__ float g_cumS [NH * S_LEN];   // inclusive scan of log_f
__device__ float g_B    [NH * S_LEN];   // B[t] = ig[t] - cum[t]
__device__ float g_pm   [NH * S_LEN];   // prefix max of B (inclusive)
__device__ float g_tileb[NH * 32];      // per-64-tile max of B
__device__ float g_h    [S_LEN * EDIM];

// bf16 hi/lo split operands
__device__ __nv_bfloat16 g_qh[S_LEN * EDIM];
__device__ __nv_bfloat16 g_ql[S_LEN * EDIM];
__device__ __nv_bfloat16 g_kh[S_LEN * EDIM];
__device__ __nv_bfloat16 g_kl[S_LEN * EDIM];
__device__ __nv_bfloat16 g_vth[NH * DH * S_LEN];   // V^T: [h][dim][seq]
__device__ __nv_bfloat16 g_vtl[NH * DH * S_LEN];

// ---------------------------------------------------------------------------
// helpers
// ---------------------------------------------------------------------------
__device__ __forceinline__ uint32_t s2u(const void* p) {
    uint32_t a;
    asm("{ .reg .u64 t; cvta.to.shared.u64 t, %1; cvt.u32.u64 %0, t; }"
        : "=r"(a) : "l"(p));
    return a;
}
__device__ __forceinline__ void cp16(uint32_t dst, const void* src) {
    asm volatile("cp.async.cg.shared.global [%0], [%1], 16;" :: "r"(dst), "l"(src));
}
__device__ __forceinline__ void cp_commit() {
    asm volatile("cp.async.commit_group;");
}
__device__ __forceinline__ void cp_wait0() {
    asm volatile("cp.async.wait_group 0;");
}
__device__ __forceinline__ void ldsm4(uint32_t (&r)[4], uint32_t addr) {
    asm volatile("ldmatrix.sync.aligned.m8n8.x4.shared.b16 {%0,%1,%2,%3}, [%4];"
                 : "=r"(r[0]), "=r"(r[1]), "=r"(r[2]), "=r"(r[3]) : "r"(addr));
}
__device__ __forceinline__ void mma16816(float (&d)[4], const uint32_t (&a)[4],
                                         uint32_t b0, uint32_t b1) {
    asm volatile(
        "mma.sync.aligned.m16n8k16.row.col.f32.bf16.bf16.f32 "
        "{%0,%1,%2,%3}, {%4,%5,%6,%7}, {%8,%9}, {%0,%1,%2,%3};"
        : "+f"(d[0]), "+f"(d[1]), "+f"(d[2]), "+f"(d[3])
        : "r"(a[0]), "r"(a[1]), "r"(a[2]), "r"(a[3]), "r"(b0), "r"(b1));
}
__device__ __forceinline__ void split_pack(float a, float b,
                                           uint32_t& hi, uint32_t& lo) {
    __nv_bfloat16 ha = __float2bfloat16(a);
    __nv_bfloat16 hb = __float2bfloat16(b);
    __nv_bfloat16 la = __float2bfloat16(a - __bfloat162float(ha));
    __nv_bfloat16 lb = __float2bfloat16(b - __bfloat162float(hb));
    __nv_bfloat162 vh; vh.x = ha; vh.y = hb;
    __nv_bfloat162 vl; vl.x = la; vl.y = lb;
    hi = *(uint32_t*)&vh;
    lo = *(uint32_t*)&vl;
}

// ---------------------------------------------------------------------------
// Kernel 1: gate projections. (unchanged, passed R11)
// ---------------------------------------------------------------------------
__global__ void gates_kernel(const float* __restrict__ q,
                             const float* __restrict__ k,
                             const float* __restrict__ v,
                             const float* __restrict__ Wi,
                             const float* __restrict__ bi,
                             const float* __restrict__ Wf,
                             const float* __restrict__ bf) {
    const int b = blockIdx.x;
    const int tid = threadIdx.x;

    float acc[64];
#pragma unroll
    for (int i = 0; i < 64; i++) acc[i] = 0.f;

#pragma unroll 1
    for (int it = 0; it < 12; it++) {
        const int j = it * 256 + tid;
        float wi[8], wf[8];
#pragma unroll
        for (int h = 0; h < 8; h++) {
            wi[h] = Wi[h * 3072 + j];
            wf[h] = Wf[h * 3072 + j];
        }
#pragma unroll
        for (int r = 0; r < 4; r++) {
            const int s = b * 4 + r;
            float x;
            if (j < 1024)       x = q[s * 1024 + j];
            else if (j < 2048)  x = k[s * 1024 + (j - 1024)];
            else                x = v[s * 1024 + (j - 2048)];
#pragma unroll
            for (int h = 0; h < 8; h++) {
                acc[r * 16 + h]     = fmaf(x, wi[h], acc[r * 16 + h]);
                acc[r * 16 + 8 + h] = fmaf(x, wf[h], acc[r * 16 + 8 + h]);
            }
        }
    }

#pragma unroll
    for (int i = 0; i < 64; i++) {
#pragma unroll
        for (int off = 16; off > 0; off >>= 1)
            acc[i] += __shfl_xor_sync(0xffffffffu, acc[i], off);
    }
    __shared__ float red[8][64];
    const int warp = tid >> 5, lane = tid & 31;
    if (lane == 0) {
#pragma unroll
        for (int i = 0; i < 64; i++) red[warp][i] = acc[i];
    }
    __syncthreads();
    if (tid < 64) {
        float vsum = 0.f;
#pragma unroll
        for (int w = 0; w < 8; w++) vsum += red[w][tid];
        const int r = tid >> 4;
        const int o = tid & 15;
        const int h = o & 7;
        const int s = b * 4 + r;
        if (o < 8) {
            g_ig[h * S_LEN + s] = vsum + bi[h];
        } else {
            const float fg = vsum + bf[h];
            g_logf[h * S_LEN + s] = fminf(fg, 0.f) - log1pf(expf(-fabsf(fg)));
        }
    }
}

// ---------------------------------------------------------------------------
// Kernel 2: per-head scan. (unchanged, passed R11)
// ---------------------------------------------------------------------------
__global__ void scan_kernel() {
    const int h = blockIdx.x;
    const int tid = threadIdx.x;
    const int lane = tid & 31, warp = tid >> 5;

    const double x0 = (double)g_logf[h * S_LEN + 2 * tid];
    const double x1 = (double)g_logf[h * S_LEN + 2 * tid + 1];
    const double s = x0 + x1;

    double inc = s;
#pragma unroll
    for (int off = 1; off < 32; off <<= 1) {
        double u = __shfl_up_sync(0xffffffffu, inc, off);
        if (lane >= off) inc += u;
    }
    __shared__ double wsum[32];
    if (lane == 31) wsum[warp] = inc;
    __syncthreads();
    if (warp == 0) {
        double w = wsum[lane];
#pragma unroll
        for (int off = 1; off < 32; off <<= 1) {
            double u = __shfl_up_sync(0xffffffffu, w, off);
            if (lane >= off) w += u;
        }
        wsum[lane] = w;
    }
    __syncthreads();
    const double base = (warp > 0) ? wsum[warp - 1] : 0.0;
    const double incl = base + inc;
    const double excl = incl - s;

    const float c0 = (float)(excl + x0);
    const float c1 = (float)incl;
    g_cumS[h * S_LEN + 2 * tid]     = c0;
    g_cumS[h * S_LEN + 2 * tid + 1] = c1;

    const float B0 = g_ig[h * S_LEN + 2 * tid]     - c0;
    const float B1 = g_ig[h * S_LEN + 2 * tid + 1] - c1;
    g_B[h * S_LEN + 2 * tid]     = B0;
    g_B[h * S_LEN + 2 * tid + 1] = B1;

    const float mx = fmaxf(B0, B1);

    float tb = mx;
#pragma unroll
    for (int off = 16; off > 0; off >>= 1)
        tb = fmaxf(tb, __shfl_xor_sync(0xffffffffu, tb, off));
    if (lane == 0) g_tileb[h * 32 + warp] = tb;

    float im = mx;
#pragma unroll
    for (int off = 1; off < 32; off <<= 1) {
        float u = __shfl_up_sync(0xffffffffu, im, off);
        if (lane >= off) im = fmaxf(im, u);
    }
    __shared__ float wm[32];
    if (lane == 31) wm[warp] = im;
    __syncthreads();
    if (warp == 0) {
        float w = wm[lane];
#pragma unroll
        for (int off = 1; off < 32; off <<= 1) {
            float u = __shfl_up_sync(0xffffffffu, w, off);
            if (lane >= off) w = fmaxf(w, u);
        }
        wm[lane] = w;
    }
    __syncthreads();
    const float bmbase = (warp > 0) ? wm[warp - 1] : -INFINITY;
    const float wexcl = __shfl_up_sync(0xffffffffu, im, 1);
    const float exclm = fmaxf(bmbase, (lane > 0) ? wexcl : -INFINITY);
    const float pm0 = fmaxf(exclm, B0);
    const float pm1 = fmaxf(pm0, B1);
    g_pm[h * S_LEN + 2 * tid]     = pm0;
    g_pm[h * S_LEN + 2 * tid + 1] = pm1;
}

// ---------------------------------------------------------------------------
// Kernel 2b: convert q,k -> bf16 hi/lo. grid 2048 x 256 (one float4 each).
// ---------------------------------------------------------------------------
__global__ void cvt_qk_kernel(const float* __restrict__ q,
                              const float* __restrict__ k) {
    const int idx = blockIdx.x * 256 + threadIdx.x;   // float4 index
    const float4 a = ((const float4*)q)[idx];
    uint32_t h0, l0, h1, l1;
    split_pack(a.x, a.y, h0, l0);
    split_pack(a.z, a.w, h1, l1);
    ((uint2*)g_qh)[idx] = make_uint2(h0, h1);
    ((uint2*)g_ql)[idx] = make_uint2(l0, l1);
    const float4 b = ((const float4*)k)[idx];
    split_pack(b.x, b.y, h0, l0);
    split_pack(b.z, b.w, h1, l1);
    ((uint2*)g_kh)[idx] = make_uint2(h0, h1);
    ((uint2*)g_kl)[idx] = make_uint2(l0, l1);
}

// ---------------------------------------------------------------------------
// Kernel 2c: convert+transpose v -> V^T bf16 hi/lo [h][dim][seq].
// grid 2048 (= 8 heads x 64 stiles x 4 dtiles) x 256.
// ---------------------------------------------------------------------------
__global__ void cvt_vt_kernel(const float* __restrict__ v) {
    const int b = blockIdx.x;
    const int h = b >> 8;
    const int rem = b & 255;
    const int st = rem >> 2, dt = rem & 3;
    const int s0 = st * 32, d0 = dt * 32;

    __shared__ float t[32][33];
    const int tid = threadIdx.x;
    const int r = tid >> 3, cg = tid & 7;

    const float4 x = *(const float4*)(v + (size_t)(s0 + r) * EDIM + h * DH + d0 + cg * 4);
    t[r][cg * 4 + 0] = x.x;
    t[r][cg * 4 + 1] = x.y;
    t[r][cg * 4 + 2] = x.z;
    t[r][cg * 4 + 3] = x.w;
    __syncthreads();

    const float y0 = t[cg * 4 + 0][r];
    const float y1 = t[cg * 4 + 1][r];
    const float y2 = t[cg * 4 + 2][r];
    const float y3 = t[cg * 4 + 3][r];
    uint32_t h0, l0, h1, l1;
    split_pack(y0, y1, h0, l0);
    split_pack(y2, y3, h1, l1);
    const size_t off = ((size_t)h * DH + d0 + r) * S_LEN + s0 + cg * 4;
    *(uint2*)(g_vth + off) = make_uint2(h0, h1);
    *(uint2*)(g_vtl + off) = make_uint2(l0, l1);
}

// ---------------------------------------------------------------------------
// Kernel 3: mma.sync (HMMA) flash mLSTM. Split-bf16 3-term.
// grid 128 = (16 qtiles of 128 rows x 8 heads), 256 threads (8 warps x m16).
// ---------------------------------------------------------------------------
#define SM_EB  0                         // eB[64] floats
#define SM_BS  256                       // Bs[64] floats
#define SM_QH  1024                      // [128][256B] swizzled = 32768
#define SM_QL  (SM_QH + 32768)
#define SM_KH  (SM_QL + 32768)           // 2 x [64][256B] = 32768
#define SM_KL  (SM_KH + 32768)
#define SM_VH  (SM_KL + 32768)           // 2 x [128][128B] = 32768
#define SM_VL  (SM_VH + 32768)
#define SM_TOTAL (SM_VL + 32768)         // 197632 bytes

extern "C" __global__ void __launch_bounds__(NT, 1)
mlstm_tc_kernel() {
    extern __shared__ char smc[];
    const uint32_t sb = s2u(smc);
    float* eB = (float*)(smc + SM_EB);
    float* Bs = (float*)(smc + SM_BS);

    const int tid  = threadIdx.x;
    const int warp = tid >> 5, lane = tid & 31;
    const int bx = blockIdx.x;
    const int qi = bx >> 3;               // 0..15
    const int h  = bx & 7;
    const int qrow0 = qi * BM;
    const int m0 = warp * 16;
    const float scale = 0.08838834764831845f;   // 1/sqrt(128)

    // ---- prefetch Q (whole CTA tile) + K0/V0, one commit group ----
    {
        const __nv_bfloat16* gq_h = g_qh + (size_t)qrow0 * EDIM + h * DH;
        const __nv_bfloat16* gq_l = g_ql + (size_t)qrow0 * EDIM + h * DH;
#pragma unroll
        for (int it = 0; it < 8; it++) {
            const int c = it * NT + tid;       // 0..2047
            const int row = c >> 4, ch = c & 15;
            const uint32_t so = (uint32_t)(row * 256 + ((ch ^ (row & 7)) << 4));
            cp16(sb + SM_QH + so, gq_h + row * EDIM + ch * 8);
            cp16(sb + SM_QL + so, gq_l + row * EDIM + ch * 8);
        }
        const __nv_bfloat16* gk_h = g_kh + h * DH;
        const __nv_bfloat16* gk_l = g_kl + h * DH;
#pragma unroll
        for (int it = 0; it < 4; it++) {
            const int c = it * NT + tid;       // 0..1023
            const int row = c >> 4, ch = c & 15;
            const uint32_t so = (uint32_t)(row * 256 + ((ch ^ (row & 7)) << 4));
            cp16(sb + SM_KH + so, gk_h + row * EDIM + ch * 8);
            cp16(sb + SM_KL + so, gk_l + row * EDIM + ch * 8);
        }
        const __nv_bfloat16* gv_h = g_vth + (size_t)h * DH * S_LEN;
        const __nv_bfloat16* gv_l = g_vtl + (size_t)h * DH * S_LEN;
#pragma unroll
        for (int it = 0; it < 4; it++) {
            const int c = it * NT + tid;       // 0..1023
            const int row = c >> 3, ch = c & 7;
            const uint32_t so = (uint32_t)(row * 128 + ((ch ^ (row & 7)) << 4));
            cp16(sb + SM_VH + so, gv_h + (size_t)row * S_LEN + ch * 8);
            cp16(sb + SM_VL + so, gv_l + (size_t)row * S_LEN + ch * 8);
        }
        cp_commit();
    }

    // per-thread row constants
    const int r0g = qrow0 + m0 + (lane >> 2);
    const int r1g = r0g + 8;
    const float pm0 = g_pm[h * S_LEN + r0g];
    const float pm1 = g_pm[h * S_LEN + r1g];
    const float cq0 = g_cumS[h * S_LEN + r0g];
    const float cq1 = g_cumS[h * S_LEN + r1g];
    float ls0 = 0.f, ls1 = 0.f;

    float O[16][4];
#pragma unroll
    for (int n = 0; n < 16; n++)
#pragma unroll
        for (int i = 0; i < 4; i++) O[n][i] = 0.f;

    const int nkt = 2 * qi + 2;
    cp_wait0();
    __syncthreads();

    for (int kt = 0; kt < nkt; kt++) {
        const int t0 = kt * BN;
        const int buf = kt & 1;

        // prefetch next K/V into other buffer (overlaps with compute)
        if (kt + 1 < nkt) {
            const int t1 = t0 + BN;
            const __nv_bfloat16* gk_h = g_kh + (size_t)t1 * EDIM + h * DH;
            const __nv_bfloat16* gk_l = g_kl + (size_t)t1 * EDIM + h * DH;
            const uint32_t kb = sb + (buf ? 0u : 16384u);
#pragma unroll
            for (int it = 0; it < 4; it++) {
                const int c = it * NT + tid;
                const int row = c >> 4, ch = c & 15;
                const uint32_t so = (uint32_t)(row * 256 + ((ch ^ (row & 7)) << 4));
                cp16(kb + SM_KH + so, gk_h + row * EDIM + ch * 8);
                cp16(kb + SM_KL + so, gk_l + row * EDIM + ch * 8);
            }
            const __nv_bfloat16* gv_h = g_vth + (size_t)h * DH * S_LEN + t1;
            const __nv_bfloat16* gv_l = g_vtl + (size_t)h * DH * S_LEN + t1;
#pragma unroll
            for (int it = 0; it < 4; it++) {
                const int c = it * NT + tid;
                const int row = c >> 3, ch = c & 7;
                const uint32_t so = (uint32_t)(row * 128 + ((ch ^ (row & 7)) << 4));
                cp16(kb + SM_VH + so, gv_h + (size_t)row * S_LEN + ch * 8);
                cp16(kb + SM_VL + so, gv_l + (size_t)row * S_LEN + ch * 8);
            }
            cp_commit();
        }

        const float tb = g_tileb[h * 32 + kt];
        if (tid < 64) {
            const float bv = g_B[h * S_LEN + t0 + tid];
            Bs[tid] = bv;
            eB[tid] = __expf(bv - tb);
        }
        __syncthreads();

        const bool active = (t0 <= qrow0 + m0 + 15);
        if (active) {
            // ---- QK^T: C[8 ntiles][4], 3 terms ----
            float C[8][4];
#pragma unroll
            for (int n = 0; n < 8; n++)
#pragma unroll
                for (int i = 0; i < 4; i++) C[n][i] = 0.f;

            const uint32_t qhb = sb + SM_QH;
            const uint32_t qlb = sb + SM_QL;
            const uint32_t khb = sb + SM_KH + buf * 16384u;
            const uint32_t klb = sb + SM_KL + buf * 16384u;
            const int arow = m0 + (lane & 15);
            const int half = lane >> 4;
            const uint32_t aro = (uint32_t)(arow * 256);
            const int asw = arow & 7;

#pragma unroll
            for (int kk = 0; kk < 8; kk++) {
                uint32_t ah[4], al[4];
                const uint32_t ach = (uint32_t)(((kk * 2 + half) ^ asw) << 4);
                ldsm4(ah, qhb + aro + ach);
                ldsm4(al, qlb + aro + ach);
#pragma unroll
                for (int g = 0; g < 4; g++) {
                    const int kr = g * 16 + (lane & 15);
                    const uint32_t ko = (uint32_t)(kr * 256 +
                                        (((kk * 2 + half) ^ (kr & 7)) << 4));
                    uint32_t bh[4], bl[4];
                    ldsm4(bh, khb + ko);
                    ldsm4(bl, klb + ko);
                    mma16816(C[2 * g],     ah, bh[0], bh[2]);
                    mma16816(C[2 * g + 1], ah, bh[1], bh[3]);
                    mma16816(C[2 * g],     ah, bl[0], bl[2]);
                    mma16816(C[2 * g + 1], ah, bl[1], bl[3]);
                    mma16816(C[2 * g],     al, bh[0], bh[2]);
                    mma16816(C[2 * g + 1], al, bh[1], bh[3]);
                }
            }

            // ---- gate epilogue -> P (in C), accumulate l ----
            if (t0 + 63 <= r0g) {
                const float eA0 = scale * __expf(tb - pm0);
                const float eA1 = scale * __expf(tb - pm1);
#pragma unroll
                for (int n = 0; n < 8; n++) {
                    const int cc = n * 8 + 2 * (lane & 3);
                    const float e0 = eB[cc], e1 = eB[cc + 1];
                    C[n][0] *= eA0 * e0; C[n][1] *= eA0 * e1;
                    C[n][2] *= eA1 * e0; C[n][3] *= eA1 * e1;
                    ls0 += C[n][0] + C[n][1];
                    ls1 += C[n][2] + C[n][3];
                }
            } else {
#pragma unroll
                for (int n = 0; n < 8; n++) {
                    const int cc = n * 8 + 2 * (lane & 3);
                    const int gc0 = t0 + cc, gc1 = gc0 + 1;
                    const float b0v = Bs[cc], b1v = Bs[cc + 1];
                    C[n][0] = (gc0 <= r0g) ? C[n][0] * (scale * __expf(b0v - pm0)) : 0.f;
                    C[n][1] = (gc1 <= r0g) ? C[n][1] * (scale * __expf(b1v - pm0)) : 0.f;
                    C[n][2] = (gc0 <= r1g) ? C[n][2] * (scale * __expf(b0v - pm1)) : 0.f;
                    C[n][3] = (gc1 <= r1g) ? C[n][3] * (scale * __expf(b1v - pm1)) : 0.f;
                    ls0 += C[n][0] + C[n][1];
                    ls1 += C[n][2] + C[n][3];
                }
            }

            // ---- P @ V: O[16 ntiles][4], 3 terms; P frags from C ----
            const uint32_t vhb = sb + SM_VH + buf * 16384u;
            const uint32_t vlb = sb + SM_VL + buf * 16384u;
#pragma unroll
            for (int j = 0; j < 4; j++) {
                uint32_t ph[4], pl[4];
                split_pack(C[2 * j][0],     C[2 * j][1],     ph[0], pl[0]);
                split_pack(C[2 * j][2],     C[2 * j][3],     ph[1], pl[1]);
                split_pack(C[2 * j + 1][0], C[2 * j + 1][1], ph[2], pl[2]);
                split_pack(C[2 * j + 1][2], C[2 * j + 1][3], ph[3], pl[3]);
#pragma unroll
                for (int g = 0; g < 8; g++) {
                    const int vr = g * 16 + (lane & 15);
                    const uint32_t vo = (uint32_t)(vr * 128 +
                                        (((j * 2 + half) ^ (vr & 7)) << 4));
                    uint32_t vh[4], vl[4];
                    ldsm4(vh, vhb + vo);
                    ldsm4(vl, vlb + vo);
                    mma16816(O[2 * g],     ph, vh[0], vh[2]);
                    mma16816(O[2 * g + 1], ph, vh[1], vh[3]);
                    mma16816(O[2 * g],     ph, vl[0], vl[2]);
                    mma16816(O[2 * g + 1], ph, vl[1], vl[3]);
                    mma16816(O[2 * g],     pl, vh[0], vh[2]);
                    mma16816(O[2 * g + 1], pl, vh[1], vh[3]);
                }
            }
        }

        cp_wait0();
        __syncthreads();
    }

    // ---- epilogue: reduce l over the quad, normalize, store ----
    ls0 += __shfl_xor_sync(0xffffffffu, ls0, 1);
    ls0 += __shfl_xor_sync(0xffffffffu, ls0, 2);
    ls1 += __shfl_xor_sync(0xffffffffu, ls1, 1);
    ls1 += __shfl_xor_sync(0xffffffffu, ls1, 2);

    const float inv0 = 1.f / (fmaxf(fabsf(ls0), __expf(-(cq0 + pm0))) + 1e-6f);
    const float inv1 = 1.f / (fmaxf(fabsf(ls1), __expf(-(cq1 + pm1))) + 1e-6f);

    float* d0 = g_h + (size_t)r0g * EDIM + h * DH;
    float* d1 = g_h + (size_t)r1g * EDIM + h * DH;
#pragma unroll
    for (int n = 0; n < 16; n++) {
        const int dd = n * 8 + 2 * (lane & 3);
        *(float2*)(d0 + dd) = make_float2(O[n][0] * inv0, O[n][1] * inv0);
        *(float2*)(d1 + dd) = make_float2(O[n][2] * inv1, O[n][3] * inv1);
    }
}

// ---------------------------------------------------------------------------
// Kernel 4: residual layer norm. (unchanged)
// ---------------------------------------------------------------------------
__global__ void ln_kernel(const float* __restrict__ lnw, float* __restrict__ out) {
    const int s = blockIdx.x;
    const int tid = threadIdx.x;
    const int lane = tid & 31, warp = tid >> 5;

    const float4 x = *(const float4*)(g_h + s * EDIM + tid * 4);

    __shared__ float wsum[8];
    __shared__ float stat[2];

    float lsum = x.x + x.y + x.z + x.w;
#pragma unroll
    for (int off = 16; off > 0; off >>= 1)
        lsum += __shfl_xor_sync(0xffffffffu, lsum, off);
    if (lane == 0) wsum[warp] = lsum;
    __syncthreads();
    if (tid == 0) {
        float t = 0.f;
#pragma unroll
        for (int w = 0; w < 8; w++) t += wsum[w];
        stat[0] = t * (1.f / 1024.f);
    }
    __syncthreads();
    const float mean = stat[0];

    const float d0 = x.x - mean, d1 = x.y - mean, d2 = x.z - mean, d3 = x.w - mean;
    float lsq = d0 * d0 + d1 * d1 + d2 * d2 + d3 * d3;
#pragma unroll
    for (int off = 16; off > 0; off >>= 1)
        lsq += __shfl_xor_sync(0xffffffffu, lsq, off);
    if (lane == 0) wsum[warp] = lsq;
    __syncthreads();
    if (tid == 0) {
        float t = 0.f;
#pragma unroll
        for (int w = 0; w < 8; w++) t += wsum[w];
        stat[1] = rsqrtf(t * (1.f / 1024.f) + 1e-5f);
    }
    __syncthreads();
    const float rstd = stat[1];

    const float4 w4 = *(const float4*)(lnw + tid * 4);
    float4 r;
    r.x = d0 * rstd * (1.f + w4.x);
    r.y = d1 * rstd * (1.f + w4.y);
    r.z = d2 * rstd * (1.f + w4.z);
    r.w = d3 * rstd * (1.f + w4.w);
    *(float4*)(out + s * EDIM + tid * 4) = r;
}

// ---------------------------------------------------------------------------
extern "C" void kernel_launch(void* const* d_in, const int* in_sizes, int n_in,
                              void* d_out, int out_size) {
    const float* q   = (const float*)d_in[0];
    const float* k   = (const float*)d_in[1];
    const float* v   = (const float*)d_in[2];
    const float* Wi  = (const float*)d_in[3];
    const float* bi  = (const float*)d_in[4];
    const float* Wf  = (const float*)d_in[5];
    const float* bf  = (const float*)d_in[6];
    const float* lnw = (const float*)d_in[7];
    float* out = (float*)d_out;

    gates_kernel<<<S_LEN / 4, 256>>>(q, k, v, Wi, bi, Wf, bf);
    scan_kernel<<<NH, 1024>>>();
    cvt_qk_kernel<<<2048, 256>>>(q, k);
    cvt_vt_kernel<<<2048, 256>>>(v);

    cudaFuncSetAttribute(mlstm_tc_kernel,
                         cudaFuncAttributeMaxDynamicSharedMemorySize, SM_TOTAL);
    mlstm_tc_kernel<<<16 * NH, NT, SM_TOTAL>>>();

    ln_kernel<<<S_LEN, 256>>>(lnw, out);
}